// round 15
// baseline (speedup 1.0000x reference)
#include <cuda_runtime.h>
#include <cuda_bf16.h>
#include <mma.h>
#include <cstdint>
#include <math.h>

using namespace nvcuda;

#define BB    8
#define TT    1024
#define HH    768
#define HD    384
#define GG    1536            // 4*HD gates per direction
#define SS    16
#define NBD   48              // blocks per direction in recurrence
#define GPB   32              // gate rows per block (GG/NBD)
#define CPB   8               // h columns per block
#define HSTR  388             // padded row stride (floats) for [b][k] / [gl][k] smem

// packed f32x2 FMA (sm_103a)
#define FMA2(d, a, b) asm("fma.rn.f32x2 %0, %1, %2, %0;" : "+l"(d) : "l"(a), "l"(b))

// ---------------- device scratch (no allocation allowed) ----------------
__device__ __align__(16) __nv_bfloat16 g_x_bf[(size_t)BB * TT * HH];        // layer input (bf16)
__device__ __align__(16) __nv_bfloat16 g_wbf[2][(size_t)2 * GG * HH];       // W_ih bf16 per layer
__device__ __align__(16) float         g_gx[(size_t)BB * TT * 2 * GG];      // input projections [8192][3072]
__device__ __align__(16) float         g_enc[(size_t)BB * TT * HH];         // fp32 layer output
__device__ __align__(16) float         g_h[2 * 2 * BB * HD];                // [parity][dir][b][k] (k packed 384)
__device__ int                         g_flags[2][2][NBD];                  // [layer][dir][block]

// ---------------- tiny kernels ----------------
__global__ void init_flags_kernel() {
    int i = threadIdx.x;
    if (i < 2 * 2 * NBD) ((int*)g_flags)[i] = 0;
}

__global__ void emb_kernel(const int* __restrict__ ids, const float* __restrict__ emb) {
    int row = blockIdx.x;                         // b*T + t
    int id  = ids[row];
    const float* src = emb + (size_t)id * HH;
    __nv_bfloat16* dst = g_x_bf + (size_t)row * HH;
    for (int i = threadIdx.x; i < HH; i += blockDim.x)
        dst[i] = __float2bfloat16_rn(src[i]);
}

__global__ void conv_w_kernel(const float* __restrict__ wf, const float* __restrict__ wb, int layer) {
    int i = blockIdx.x * blockDim.x + threadIdx.x;     // over 2*GG*HH = 2359296
    if (i < 2 * GG * HH) {
        float v = (i < GG * HH) ? wf[i] : wb[i - GG * HH];
        g_wbf[layer][i] = __float2bfloat16_rn(v);
    }
}

// ---------------- input-projection GEMM: gx[8192,3072] = X[8192,768] * W[3072,768]^T ----------------
__global__ __launch_bounds__(256) void gemm_bf16_kernel(const __nv_bfloat16* __restrict__ Bw) {
    __shared__ __align__(16) __nv_bfloat16 As[64][48];
    __shared__ __align__(16) __nv_bfloat16 Bs[128][48];

    const __nv_bfloat16* __restrict__ A = g_x_bf;
    float* __restrict__ C = g_gx;

    int tid = threadIdx.x;
    int m0 = blockIdx.y * 64;
    int n0 = blockIdx.x * 128;
    int warp = tid >> 5;
    int wm = warp >> 2, wn = warp & 3;      // 2 x 4 warps

    wmma::fragment<wmma::accumulator, 16, 16, 16, float> acc[2][2];
#pragma unroll
    for (int i = 0; i < 2; i++)
#pragma unroll
        for (int j = 0; j < 2; j++) wmma::fill_fragment(acc[i][j], 0.0f);

    for (int k0 = 0; k0 < HH; k0 += 32) {
        {
            int r = tid >> 2, c = (tid & 3) * 8;   // 64 rows x 32 k
            *(uint4*)&As[r][c] = *(const uint4*)&A[(size_t)(m0 + r) * HH + k0 + c];
        }
#pragma unroll
        for (int i = 0; i < 2; i++) {
            int idx = tid + i * 256;
            int r = idx >> 2, c = (idx & 3) * 8;   // 128 rows x 32 k
            *(uint4*)&Bs[r][c] = *(const uint4*)&Bw[(size_t)(n0 + r) * HH + k0 + c];
        }
        __syncthreads();
#pragma unroll
        for (int kf = 0; kf < 32; kf += 16) {
            wmma::fragment<wmma::matrix_a, 16, 16, 16, __nv_bfloat16, wmma::row_major> af[2];
            wmma::fragment<wmma::matrix_b, 16, 16, 16, __nv_bfloat16, wmma::col_major> bf[2];
            wmma::load_matrix_sync(af[0], &As[wm * 32][kf], 48);
            wmma::load_matrix_sync(af[1], &As[wm * 32 + 16][kf], 48);
            wmma::load_matrix_sync(bf[0], &Bs[wn * 32][kf], 48);
            wmma::load_matrix_sync(bf[1], &Bs[wn * 32 + 16][kf], 48);
#pragma unroll
            for (int i = 0; i < 2; i++)
#pragma unroll
                for (int j = 0; j < 2; j++)
                    wmma::mma_sync(acc[i][j], af[i], bf[j], acc[i][j]);
        }
        __syncthreads();
    }
#pragma unroll
    for (int i = 0; i < 2; i++)
#pragma unroll
        for (int j = 0; j < 2; j++)
            wmma::store_matrix_sync(&C[(size_t)(m0 + wm * 32 + i * 16) * (2 * GG) + n0 + wn * 32 + j * 16],
                                    acc[i][j], 2 * GG, wmma::mem_row_major);
}

// ---------------- recurrence: 96 persistent blocks (48/dir) ----------------
// lane role: gl = warp*4 + (lane>>3) (gate row 0..31), b = lane&7. Each thread computes the FULL
// 384-k dot for (gl, b) via FMA2 over k-pairs: W pairs from smem [gl][k] (4x16B broadcast groups,
// conflict-free), h pairs from smem [b][k] stride 388 (8 distinct quads, conflict-free).
// No cross-warp reduce. Finalize (tid<64) consumes gate_sh, keeps c in a register, writes h to
// g_h [b][k] + own slice directly into h_sh, then bar.sync(1,64) + st.release flag.
#define RSMEM_FLOATS (GPB * HSTR + BB * HSTR + 256)
#define RSMEM_BYTES  (RSMEM_FLOATS * 4)

__global__ __launch_bounds__(256) void recur_kernel(
    int layer,
    const float* __restrict__ whh_f, const float* __restrict__ whh_b,
    const float* __restrict__ bih_f, const float* __restrict__ bhh_f,
    const float* __restrict__ bih_b, const float* __restrict__ bhh_b)
{
    extern __shared__ __align__(16) float sm[];
    float* w_sm    = sm;                        // [gl][k] stride HSTR
    float* h_sh    = sm + GPB * HSTR;           // [b][k]  stride HSTR
    float* gate_sh = sm + GPB * HSTR + BB * HSTR;   // [gl][b]

    int tid = threadIdx.x;
    int dir = blockIdx.x / NBD;             // 0 fwd, 1 bwd
    int bi  = blockIdx.x - dir * NBD;
    int col0 = bi * CPB;

    const float* whh = dir ? whh_b : whh_f;

    // stage W_hh slice: gl -> global gate row (gl>>3)*HD + col0 + (gl&7)
    for (int i = tid; i < GPB * HD; i += 256) {
        int gl = i / HD, k = i - gl * HD;
        int grow = (gl >> 3) * HD + col0 + (gl & 7);
        w_sm[gl * HSTR + k] = whh[(size_t)grow * HD + k];
    }

    int lane = tid & 31, warp = tid >> 5;
    int gl = warp * 4 + (lane >> 3);        // 0..31
    int b  = lane & 7;
    int grow = (gl >> 3) * HD + col0 + (gl & 7);
    float bias_r = dir ? (bih_b[grow] + bhh_b[grow]) : (bih_f[grow] + bhh_f[grow]);

    int* myflag = &g_flags[layer][dir][bi];
    int* pollflag = &g_flags[layer][dir][tid < NBD ? tid : 0];
    bool do_poll = (tid < NBD) && (tid != bi);

    const ulonglong2* wrow = (const ulonglong2*)(w_sm + gl * HSTR);
    const ulonglong2* hrow = (const ulonglong2*)(h_sh + b * HSTR);

    float c_reg = 0.0f;                     // cell state for finalize threads (tid<64)
    int fin_c = tid >> 3, fin_b = tid & 7;  // finalize role

    // copy-role precompute: thread handles float4 indices tid, tid+256, tid+512 of 768
    // q -> b_q = q/96, kq = q%96 ; own slice iff (kq>>1) == col0>>3
    __syncthreads();

    for (int ti = 0; ti < TT; ++ti) {
        int t = dir ? (TT - 1 - ti) : ti;

        // prefetch input-projection value (independent of h) — in flight during poll/copy
        float gxv = __ldg(&g_gx[(size_t)(b * TT + t) * (2 * GG) + dir * GG + grow]);

        if (ti == 0) {
            for (int i = tid; i < BB * HSTR; i += 256) h_sh[i] = 0.0f;
            __syncthreads();
        } else {
            if (do_poll) {                      // 47 lanes poll 47 distinct remote flags
                int v;
                do {
                    asm volatile("ld.acquire.gpu.b32 %0, [%1];" : "=r"(v) : "l"(pollflag) : "memory");
                } while (v < ti);
            }
            __syncthreads();
            const float4* src = (const float4*)(g_h + ((size_t)(ti & 1) * 2 + dir) * (BB * HD));
#pragma unroll
            for (int qq = 0; qq < 3; qq++) {
                int q = tid + qq * 256;
                int b_q = q / 96, kq = q - b_q * 96;
                if ((kq >> 1) != (col0 >> 3)) {     // skip own slice (written locally by finalize)
                    float4 v = __ldcg(&src[q]);
                    *(float4*)(h_sh + b_q * HSTR + kq * 4) = v;
                }
            }
            __syncthreads();
        }

        // full-K dot for (gl, b): 96 k-quads, FMA2 over k-pairs
        unsigned long long a0 = 0ull, a1 = 0ull, a2 = 0ull, a3 = 0ull;
#pragma unroll 12
        for (int q = 0; q < 96; q += 2) {
            ulonglong2 wv0 = wrow[q],     hv0 = hrow[q];
            ulonglong2 wv1 = wrow[q + 1], hv1 = hrow[q + 1];
            FMA2(a0, wv0.x, hv0.x);
            FMA2(a1, wv0.y, hv0.y);
            FMA2(a2, wv1.x, hv1.x);
            FMA2(a3, wv1.y, hv1.y);
        }
        {
            float2 f0 = *(float2*)&a0, f1 = *(float2*)&a1, f2 = *(float2*)&a2, f3 = *(float2*)&a3;
            gate_sh[gl * 8 + b] = f0.x + f0.y + f1.x + f1.y + f2.x + f2.y + f3.x + f3.y + gxv + bias_r;
        }
        __syncthreads();

        // finalize: 64 threads own (column c, batch b)
        if (tid < 64) {
            int c = fin_c, bb = fin_b;
            float iv = gate_sh[(0 * 8 + c) * 8 + bb];
            float fv = gate_sh[(1 * 8 + c) * 8 + bb];
            float gv = gate_sh[(2 * 8 + c) * 8 + bb];
            float ov = gate_sh[(3 * 8 + c) * 8 + bb];
            float si = __fdividef(1.0f, 1.0f + __expf(-iv));
            float sf = __fdividef(1.0f, 1.0f + __expf(-fv));
            float so = __fdividef(1.0f, 1.0f + __expf(-ov));
            float tg = 1.0f - __fdividef(2.0f, __expf(2.0f * gv) + 1.0f);
            float cn = sf * c_reg + si * tg;
            float th = 1.0f - __fdividef(2.0f, __expf(2.0f * cn) + 1.0f);
            float hn = so * th;
            c_reg = cn;
            int col = col0 + c;
            // global h for remote blocks ([b][k] packed), local h_sh slice for own block
            g_h[((size_t)((ti + 1) & 1) * 2 + dir) * (BB * HD) + bb * HD + col] = hn;
            h_sh[bb * HSTR + col] = hn;
            size_t eidx = (size_t)(bb * TT + t) * HH + dir * HD + col;
            g_enc[eidx]  = hn;
            g_x_bf[eidx] = __float2bfloat16_rn(hn);
            asm volatile("bar.sync 1, 64;" ::: "memory");
            if (tid == 0)
                asm volatile("st.release.gpu.b32 [%0], %1;" :: "l"(myflag), "r"(ti + 1) : "memory");
        }
        // warps 2-7 race ahead to the next poll; phase alignment holds (1 bar0/iter for all)
    }
}

// ---------------- segment mean pool + MLP scorer ----------------
__global__ __launch_bounds__(256) void pool_mlp_kernel(
    const int* __restrict__ sb,
    const float* __restrict__ w1, const float* __restrict__ b1,
    const float* __restrict__ w2, const float* __restrict__ b2,
    float* __restrict__ out)
{
    __shared__ float mean_sh[HH];
    __shared__ float red[8];

    int b = blockIdx.x >> 4, s = blockIdx.x & 15;
    int tid = threadIdx.x;
    int end = sb[b * SS + s];
    int start = s ? sb[b * SS + s - 1] : 0;
    float inv = 1.0f / fmaxf((float)(end - start), 1.0f);

    float a0 = 0.f, a1 = 0.f, a2 = 0.f;
    for (int t = start; t < end; t++) {
        const float* row = g_enc + (size_t)(b * TT + t) * HH;
        a0 += row[tid]; a1 += row[tid + 256]; a2 += row[tid + 512];
    }
    mean_sh[tid] = a0 * inv; mean_sh[tid + 256] = a1 * inv; mean_sh[tid + 512] = a2 * inv;
    __syncthreads();

    int warp = tid >> 5, lane = tid & 31;
    float wpart = 0.f;
    for (int j = warp; j < HD; j += 8) {
        const float* wr = w1 + (size_t)j * HH;
        float acc = 0.f;
        for (int d = lane; d < HH; d += 32) acc += mean_sh[d] * wr[d];
#pragma unroll
        for (int o = 16; o; o >>= 1) acc += __shfl_xor_sync(0xFFFFFFFFu, acc, o);
        if (lane == 0) {
            float h = fmaxf(acc + b1[j], 0.0f);
            wpart += h * w2[j];
        }
    }
    if (lane == 0) red[warp] = wpart;
    __syncthreads();
    if (tid == 0) {
        float h2 = b2[0];
#pragma unroll
        for (int w = 0; w < 8; w++) h2 += red[w];
        out[b * SS + s] = 1.0f / (1.0f + expf(-h2));
    }
}

__global__ void min_kernel(float* __restrict__ out) {
    int b = threadIdx.x;
    if (b < BB) {
        float m = 1e30f;
        for (int s = 0; s < SS; s++) {
            float r = out[b * SS + s];
            float mask = (r > 0.0f) ? 1.0f : 0.0f;
            float v = r * mask + (1.0f - mask);
            m = fminf(m, v);
        }
        out[BB * SS + b] = m;
    }
}

// ---------------- launch ----------------
extern "C" void kernel_launch(void* const* d_in, const int* in_sizes, int n_in,
                              void* d_out, int out_size) {
    const int*   ids = (const int*)d_in[0];
    const int*   sb  = (const int*)d_in[1];
    const float* emb = (const float*)d_in[2];
    const float* w_ih_l0f = (const float*)d_in[3];
    const float* w_hh_l0f = (const float*)d_in[4];
    const float* b_ih_l0f = (const float*)d_in[5];
    const float* b_hh_l0f = (const float*)d_in[6];
    const float* w_ih_l0b = (const float*)d_in[7];
    const float* w_hh_l0b = (const float*)d_in[8];
    const float* b_ih_l0b = (const float*)d_in[9];
    const float* b_hh_l0b = (const float*)d_in[10];
    const float* w_ih_l1f = (const float*)d_in[11];
    const float* w_hh_l1f = (const float*)d_in[12];
    const float* b_ih_l1f = (const float*)d_in[13];
    const float* b_hh_l1f = (const float*)d_in[14];
    const float* w_ih_l1b = (const float*)d_in[15];
    const float* w_hh_l1b = (const float*)d_in[16];
    const float* b_ih_l1b = (const float*)d_in[17];
    const float* b_hh_l1b = (const float*)d_in[18];
    const float* w1 = (const float*)d_in[19];
    const float* b1 = (const float*)d_in[20];
    const float* w2 = (const float*)d_in[21];
    const float* b2 = (const float*)d_in[22];
    float* out = (float*)d_out;

    cudaFuncSetAttribute((const void*)recur_kernel,
                         cudaFuncAttributeMaxDynamicSharedMemorySize, RSMEM_BYTES);

    init_flags_kernel<<<1, 256>>>();
    emb_kernel<<<BB * TT, 256>>>(ids, emb);

    int nconv = 2 * GG * HH;
    conv_w_kernel<<<(nconv + 255) / 256, 256>>>(w_ih_l0f, w_ih_l0b, 0);
    conv_w_kernel<<<(nconv + 255) / 256, 256>>>(w_ih_l1f, w_ih_l1b, 1);

    dim3 ggrid(2 * GG / 128, BB * TT / 64);   // (24, 128)

    __nv_bfloat16* wptr = nullptr;
    cudaGetSymbolAddress((void**)&wptr, g_wbf);

    // layer 0
    gemm_bf16_kernel<<<ggrid, 256>>>(wptr);
    recur_kernel<<<2 * NBD, 256, RSMEM_BYTES>>>(0, w_hh_l0f, w_hh_l0b,
                                                b_ih_l0f, b_hh_l0f, b_ih_l0b, b_hh_l0b);
    // layer 1
    gemm_bf16_kernel<<<ggrid, 256>>>(wptr + (size_t)2 * GG * HH);
    recur_kernel<<<2 * NBD, 256, RSMEM_BYTES>>>(1, w_hh_l1f, w_hh_l1b,
                                                b_ih_l1f, b_hh_l1f, b_ih_l1b, b_hh_l1b);

    pool_mlp_kernel<<<BB * SS, 256>>>(sb, w1, b1, w2, b2, out);
    if (out_size >= BB * SS + BB)
        min_kernel<<<1, 32>>>(out);
}